// round 6
// baseline (speedup 1.0000x reference)
#include <cuda_runtime.h>
#include <cuda_bf16.h>
#include <cstdint>

// ---------------------------------------------------------------------------
// Problem constants
// ---------------------------------------------------------------------------
#define BATCH   2
#define SEQ     3072
#define DMODEL  512
#define NHEADS  8
#define DHEAD   64
#define MROWS   (BATCH * SEQ)      // 6144
#define MAXNB   32
#define CAP     256

typedef unsigned long long u64;
typedef unsigned int u32;

// ---------------------------------------------------------------------------
// Scratch (static device memory; no allocations allowed)
// ---------------------------------------------------------------------------
__device__ float g_Q[MROWS * DMODEL];
__device__ float g_K[MROWS * DMODEL];
__device__ float g_V[MROWS * DMODEL];
__device__ int   g_nbr[MROWS * MAXNB];
__device__ int   g_cnt[MROWS];

// bf16 hi/lo splits
__device__ __nv_bfloat16 g_xh[MROWS * DMODEL];
__device__ __nv_bfloat16 g_xl[MROWS * DMODEL];
__device__ __nv_bfloat16 g_ah[MROWS * DMODEL];
__device__ __nv_bfloat16 g_al[MROWS * DMODEL];
// transposed weights [n][k], 4 matrices (q,k,v,o)
__device__ __nv_bfloat16 g_wth[4 * DMODEL * DMODEL];
__device__ __nv_bfloat16 g_wtl[4 * DMODEL * DMODEL];

// ---------------------------------------------------------------------------
// helpers
// ---------------------------------------------------------------------------
__device__ __forceinline__ void split1(float v, __nv_bfloat16& h, __nv_bfloat16& l) {
    h = __float2bfloat16(v);
    l = __float2bfloat16(v - __bfloat162float(h));
}

__global__ void __launch_bounds__(256)
split_x_kernel(const float* __restrict__ x)
{
    const int i = blockIdx.x * blockDim.x + threadIdx.x;   // float4 index
    const float4 v = ((const float4*)x)[i];
    __nv_bfloat16 h0, h1, h2, h3, l0, l1, l2, l3;
    split1(v.x, h0, l0); split1(v.y, h1, l1);
    split1(v.z, h2, l2); split1(v.w, h3, l3);
    __nv_bfloat162* hp = (__nv_bfloat162*)g_xh;
    __nv_bfloat162* lp = (__nv_bfloat162*)g_xl;
    hp[2 * i]     = __nv_bfloat162(h0, h1);
    hp[2 * i + 1] = __nv_bfloat162(h2, h3);
    lp[2 * i]     = __nv_bfloat162(l0, l1);
    lp[2 * i + 1] = __nv_bfloat162(l2, l3);
}

// W[k][n] -> Wt[n][k] hi/lo, 4 matrices via blockIdx.z
__global__ void __launch_bounds__(1024)
transpose_split_kernel(const float* __restrict__ Wq, const float* __restrict__ Wk,
                       const float* __restrict__ Wv, const float* __restrict__ Wo)
{
    __shared__ float t[32][33];
    const float* W = (blockIdx.z == 0) ? Wq : (blockIdx.z == 1) ? Wk
                   : (blockIdx.z == 2) ? Wv : Wo;
    __nv_bfloat16* Th = g_wth + blockIdx.z * DMODEL * DMODEL;
    __nv_bfloat16* Tl = g_wtl + blockIdx.z * DMODEL * DMODEL;

    const int n = blockIdx.x * 32 + threadIdx.x;
    const int k = blockIdx.y * 32 + threadIdx.y;
    t[threadIdx.y][threadIdx.x] = W[k * DMODEL + n];
    __syncthreads();
    const int no = blockIdx.x * 32 + threadIdx.y;
    const int ko = blockIdx.y * 32 + threadIdx.x;
    const float v = t[threadIdx.x][threadIdx.y];
    __nv_bfloat16 h, l; split1(v, h, l);
    Th[no * DMODEL + ko] = h;
    Tl[no * DMODEL + ko] = l;
}

// ---------------------------------------------------------------------------
// Tensor-core GEMM — exact Round-3 body (measured fastest: qkv 109.3us).
// C = A @ Wt^T + bias, 3-term bf16 split (Ah*Bh + Al*Bh + Ah*Bl).
// CTA 128x128, BK=32, 8 warps (4M x 2N), warp tile 32x64, scalar LDS frags.
// ---------------------------------------------------------------------------
#define ASTR 40    // smem row stride in bf16 elems (80B)

__device__ __forceinline__ void mma16816(float* c, const u32* a, u32 b0, u32 b1) {
    asm volatile(
        "mma.sync.aligned.m16n8k16.row.col.f32.bf16.bf16.f32 "
        "{%0,%1,%2,%3}, {%4,%5,%6,%7}, {%8,%9}, {%0,%1,%2,%3};"
        : "+f"(c[0]), "+f"(c[1]), "+f"(c[2]), "+f"(c[3])
        : "r"(a[0]), "r"(a[1]), "r"(a[2]), "r"(a[3]), "r"(b0), "r"(b1));
}

__device__ __forceinline__ void tc_gemm_body(const __nv_bfloat16* __restrict__ Ah,
                                             const __nv_bfloat16* __restrict__ Al,
                                             const __nv_bfloat16* __restrict__ Bh,
                                             const __nv_bfloat16* __restrict__ Bl,
                                             const float* __restrict__ bias,
                                             float* __restrict__ C)
{
    __shared__ __nv_bfloat16 sAh[128 * ASTR];
    __shared__ __nv_bfloat16 sAl[128 * ASTR];
    __shared__ __nv_bfloat16 sBh[128 * ASTR];
    __shared__ __nv_bfloat16 sBl[128 * ASTR];

    const int tid  = threadIdx.x;
    const int w    = tid >> 5;
    const int lane = tid & 31;
    const int g    = lane >> 2;       // 0..7
    const int t2   = (lane & 3) * 2;  // 0,2,4,6
    const int wm   = w & 3;           // M warp (32 rows)
    const int wn   = w >> 2;          // N warp (64 cols)
    const int m0   = blockIdx.y * 128;
    const int n0   = blockIdx.x * 128;

    const int lr  = tid >> 2;
    const int lc  = (tid & 3) * 8;

    float acc[2][8][4];
    #pragma unroll
    for (int i = 0; i < 2; ++i)
        #pragma unroll
        for (int j = 0; j < 8; ++j)
            #pragma unroll
            for (int q = 0; q < 4; ++q) acc[i][j][q] = 0.f;

    for (int kc = 0; kc < DMODEL / 32; ++kc) {
        const size_t eA0 = (size_t)(m0 + lr) * DMODEL + kc * 32 + lc;
        const size_t eA1 = eA0 + (size_t)64 * DMODEL;
        const size_t eB0 = (size_t)(n0 + lr) * DMODEL + kc * 32 + lc;
        const size_t eB1 = eB0 + (size_t)64 * DMODEL;
        const uint4 vah0 = *(const uint4*)(Ah + eA0);
        const uint4 vah1 = *(const uint4*)(Ah + eA1);
        const uint4 val0 = *(const uint4*)(Al + eA0);
        const uint4 val1 = *(const uint4*)(Al + eA1);
        const uint4 vbh0 = *(const uint4*)(Bh + eB0);
        const uint4 vbh1 = *(const uint4*)(Bh + eB1);
        const uint4 vbl0 = *(const uint4*)(Bl + eB0);
        const uint4 vbl1 = *(const uint4*)(Bl + eB1);

        __syncthreads();   // previous tile fully consumed
        *(uint4*)(sAh + lr * ASTR + lc)        = vah0;
        *(uint4*)(sAh + (lr + 64) * ASTR + lc) = vah1;
        *(uint4*)(sAl + lr * ASTR + lc)        = val0;
        *(uint4*)(sAl + (lr + 64) * ASTR + lc) = val1;
        *(uint4*)(sBh + lr * ASTR + lc)        = vbh0;
        *(uint4*)(sBh + (lr + 64) * ASTR + lc) = vbh1;
        *(uint4*)(sBl + lr * ASTR + lc)        = vbl0;
        *(uint4*)(sBl + (lr + 64) * ASTR + lc) = vbl1;
        __syncthreads();

        #pragma unroll
        for (int ks = 0; ks < 32; ks += 16) {
            u32 ah[2][4], al[2][4];
            #pragma unroll
            for (int ma = 0; ma < 2; ++ma) {
                const int row = wm * 32 + ma * 16 + g;
                ah[ma][0] = *(const u32*)(sAh + row * ASTR + ks + t2);
                ah[ma][1] = *(const u32*)(sAh + (row + 8) * ASTR + ks + t2);
                ah[ma][2] = *(const u32*)(sAh + row * ASTR + ks + t2 + 8);
                ah[ma][3] = *(const u32*)(sAh + (row + 8) * ASTR + ks + t2 + 8);
                al[ma][0] = *(const u32*)(sAl + row * ASTR + ks + t2);
                al[ma][1] = *(const u32*)(sAl + (row + 8) * ASTR + ks + t2);
                al[ma][2] = *(const u32*)(sAl + row * ASTR + ks + t2 + 8);
                al[ma][3] = *(const u32*)(sAl + (row + 8) * ASTR + ks + t2 + 8);
            }
            #pragma unroll
            for (int na = 0; na < 8; ++na) {
                const int nrow = wn * 64 + na * 8 + g;
                const u32 bh0 = *(const u32*)(sBh + nrow * ASTR + ks + t2);
                const u32 bh1 = *(const u32*)(sBh + nrow * ASTR + ks + t2 + 8);
                const u32 bl0 = *(const u32*)(sBl + nrow * ASTR + ks + t2);
                const u32 bl1 = *(const u32*)(sBl + nrow * ASTR + ks + t2 + 8);
                #pragma unroll
                for (int ma = 0; ma < 2; ++ma) {
                    mma16816(acc[ma][na], ah[ma], bh0, bh1);
                    mma16816(acc[ma][na], al[ma], bh0, bh1);
                    mma16816(acc[ma][na], ah[ma], bl0, bl1);
                }
            }
        }
    }

    // epilogue
    #pragma unroll
    for (int ma = 0; ma < 2; ++ma) {
        const int row = m0 + wm * 32 + ma * 16 + g;
        #pragma unroll
        for (int na = 0; na < 8; ++na) {
            const int col = n0 + wn * 64 + na * 8 + t2;
            const float b0 = bias[col], b1 = bias[col + 1];
            float2 o0; o0.x = acc[ma][na][0] + b0; o0.y = acc[ma][na][1] + b1;
            float2 o1; o1.x = acc[ma][na][2] + b0; o1.y = acc[ma][na][3] + b1;
            *(float2*)(C + (size_t)row * DMODEL + col) = o0;
            *(float2*)(C + (size_t)(row + 8) * DMODEL + col) = o1;
        }
    }
}

__global__ void __launch_bounds__(256, 2)
gemm_qkv_kernel(const float* __restrict__ bq, const float* __restrict__ bk,
                const float* __restrict__ bv)
{
    const int z = blockIdx.z;
    const __nv_bfloat16* Bh = g_wth + (size_t)z * DMODEL * DMODEL;
    const __nv_bfloat16* Bl = g_wtl + (size_t)z * DMODEL * DMODEL;
    const float* bias = (z == 0) ? bq : (z == 1) ? bk : bv;
    float* C = (z == 0) ? g_Q : (z == 1) ? g_K : g_V;
    tc_gemm_body(g_xh, g_xl, Bh, Bl, bias, C);
}

__global__ void __launch_bounds__(256, 2)
gemm_out_kernel(const float* __restrict__ bo, float* __restrict__ out)
{
    const __nv_bfloat16* Bh = g_wth + (size_t)3 * DMODEL * DMODEL;
    const __nv_bfloat16* Bl = g_wtl + (size_t)3 * DMODEL * DMODEL;
    tc_gemm_body(g_ah, g_al, Bh, Bl, bo, out);
}

// ---------------------------------------------------------------------------
// Top-k neighbor selection (unchanged — known correct)
// ---------------------------------------------------------------------------
__global__ void __launch_bounds__(256)
topk_kernel(const float* __restrict__ positions)
{
    extern __shared__ float fsm[];
    float* px = fsm;
    float* py = fsm + SEQ;
    float* pz = fsm + 2 * SEQ;
    u64*  cand = (u64*)(fsm + 3 * SEQ);

    const int tid  = threadIdx.x;
    const int warp = tid >> 5;
    const int lane = tid & 31;
    const int r0   = blockIdx.x * 8;
    const int b    = r0 / SEQ;
    const int sbase = b * SEQ;

    for (int i = tid; i < SEQ; i += 256) {
        const float* p = positions + (size_t)(sbase + i) * 3;
        px[i] = p[0]; py[i] = p[1]; pz[i] = p[2];
    }
    __syncthreads();

    const int row = r0 + warp;
    const int si  = row - sbase;
    const float qx = px[si], qy = py[si], qz = pz[si];
    u64* mycand = cand + warp * CAP;

    int cnt = 0;
    for (int t = 0; t < SEQ / 32; ++t) {
        const int j = t * 32 + lane;
        const float dx = px[j] - qx, dy = py[j] - qy, dz = pz[j] - qz;
        const float dist = sqrtf(dx * dx + dy * dy + dz * dz);
        const bool in = dist < 0.5f;
        const unsigned msk = __ballot_sync(0xffffffffu, in);
        if (in) {
            const int pos = cnt + __popc(msk & ((1u << lane) - 1u));
            if (pos < CAP)
                mycand[pos] = ((u64)__float_as_uint(dist) << 32) | (unsigned)j;
        }
        cnt += __popc(msk);
    }
    if (cnt > CAP) cnt = CAP;
    __syncwarp();

    if (cnt <= MAXNB) {
        if (lane < cnt)
            g_nbr[row * MAXNB + lane] = sbase + (int)(mycand[lane] & 0xffffffffull);
        if (lane == 0) g_cnt[row] = cnt;
    } else {
        for (int sel = 0; sel < MAXNB; ++sel) {
            u64 best = ~0ull; int bslot = 0;
            for (int s2 = lane; s2 < cnt; s2 += 32) {
                const u64 kk = mycand[s2];
                if (kk < best) { best = kk; bslot = s2; }
            }
            #pragma unroll
            for (int off = 16; off; off >>= 1) {
                const u64 ob = __shfl_xor_sync(0xffffffffu, best, off);
                const int os = __shfl_xor_sync(0xffffffffu, bslot, off);
                if (ob < best) { best = ob; bslot = os; }
            }
            if (lane == 0) {
                g_nbr[row * MAXNB + sel] = sbase + (int)(best & 0xffffffffull);
                mycand[bslot] = ~0ull;
            }
            __syncwarp();
        }
        if (lane == 0) g_cnt[row] = MAXNB;
    }
}

// ---------------------------------------------------------------------------
// Sparse attention — warp-per-row, 8 rows/CTA (grid 768, 5.2 waves).
// All synchronization warp-scoped. Per lane: ~128 independent 16B loads in
// both the K-score phase and the V phase. Fused bf16 hi/lo output split.
//   QK  : lane = neighbor; per head, dot over 64 dims (q from smem broadcast)
//   soft: shfl reductions per head
//   AV  : lane = 16-dim slice (head = lane/4); loop neighbors, coalesced V
// ---------------------------------------------------------------------------
__global__ void __launch_bounds__(256)
attn_kernel()
{
    __shared__ float s_q [8][DMODEL];         // 16 KB
    __shared__ float s_p [8][NHEADS][MAXNB];  // 8 KB
    __shared__ int   s_nb[8][MAXNB];          // 1 KB

    const int tid  = threadIdx.x;
    const int w    = tid >> 5;
    const int lane = tid & 31;
    const int row  = blockIdx.x * 8 + w;
    const int m    = g_cnt[row];

    const int nb = (lane < m) ? g_nbr[row * MAXNB + lane] : 0;
    s_nb[w][lane] = nb;

    // stage q row (2KB) into smem, coalesced
    {
        const float4* qg = (const float4*)&g_Q[(size_t)row * DMODEL];
        float4* qs = (float4*)s_q[w];
        #pragma unroll
        for (int i = 0; i < 4; ++i) qs[lane + 32 * i] = qg[lane + 32 * i];
    }
    __syncwarp();

    // ---- scores: lane = neighbor, all 8 heads (128 independent loads)
    float acc[NHEADS];
    #pragma unroll
    for (int h = 0; h < NHEADS; ++h) acc[h] = 0.f;

    const float* krow = &g_K[(size_t)nb * DMODEL];
    #pragma unroll 2
    for (int h = 0; h < NHEADS; ++h) {
        const float4* kh = (const float4*)(krow + h * DHEAD);
        const float4* qh = (const float4*)(s_q[w] + h * DHEAD);
        float a = 0.f;
        #pragma unroll
        for (int c = 0; c < DHEAD / 4; ++c) {
            const float4 kv = kh[c];
            const float4 qv = qh[c];
            a += kv.x * qv.x + kv.y * qv.y + kv.z * qv.z + kv.w * qv.w;
        }
        acc[h] = a;
    }

    // ---- softmax per head across lanes
    #pragma unroll
    for (int h = 0; h < NHEADS; ++h) {
        float s = (lane < m) ? acc[h] * 0.125f : __int_as_float(0xff800000);
        float mx = s;
        #pragma unroll
        for (int off = 16; off; off >>= 1)
            mx = fmaxf(mx, __shfl_xor_sync(0xffffffffu, mx, off));
        float e = __expf(s - mx);
        float su = e;
        #pragma unroll
        for (int off = 16; off; off >>= 1)
            su += __shfl_xor_sync(0xffffffffu, su, off);
        s_p[w][h][lane] = e / su;
    }
    __syncwarp();

    // ---- AV: lane owns dims [lane*16, lane*16+16), head = lane/4
    float o[16];
    #pragma unroll
    for (int c = 0; c < 16; ++c) o[c] = 0.f;
    const int hh  = lane >> 2;
    const int dof = lane * 16;

    for (int j = 0; j < m; ++j) {
        const float pj = s_p[w][hh][j];
        const float4* vv = (const float4*)&g_V[(size_t)s_nb[w][j] * DMODEL + dof];
        #pragma unroll
        for (int c = 0; c < 4; ++c) {
            const float4 v = vv[c];
            o[4 * c + 0] += pj * v.x;
            o[4 * c + 1] += pj * v.y;
            o[4 * c + 2] += pj * v.z;
            o[4 * c + 3] += pj * v.w;
        }
    }

    // ---- fused bf16 hi/lo split (feeds gemm_out directly)
    const size_t ob = (size_t)row * DMODEL + dof;
    #pragma unroll
    for (int c = 0; c < 16; c += 2) {
        __nv_bfloat16 h0, l0, h1, l1;
        split1(o[c],     h0, l0);
        split1(o[c + 1], h1, l1);
        *(__nv_bfloat162*)&g_ah[ob + c] = __nv_bfloat162(h0, h1);
        *(__nv_bfloat162*)&g_al[ob + c] = __nv_bfloat162(l0, l1);
    }
}

// ---------------------------------------------------------------------------
// Launch
// ---------------------------------------------------------------------------
extern "C" void kernel_launch(void* const* d_in, const int* in_sizes, int n_in,
                              void* d_out, int out_size)
{
    (void)in_sizes; (void)n_in; (void)out_size;
    const float* x   = (const float*)d_in[0];
    const float* pos = (const float*)d_in[1];
    const float* Wq  = (const float*)d_in[2];
    const float* bq  = (const float*)d_in[3];
    const float* Wk  = (const float*)d_in[4];
    const float* bk  = (const float*)d_in[5];
    const float* Wv  = (const float*)d_in[6];
    const float* bv  = (const float*)d_in[7];
    const float* Wo  = (const float*)d_in[8];
    const float* bo  = (const float*)d_in[9];
    float* out = (float*)d_out;

    const int topk_smem = 3 * SEQ * 4 + 8 * CAP * 8;
    cudaFuncSetAttribute(topk_kernel,
                         cudaFuncAttributeMaxDynamicSharedMemorySize, topk_smem);

    topk_kernel<<<MROWS / 8, 256, topk_smem>>>(pos);
    transpose_split_kernel<<<dim3(16, 16, 4), dim3(32, 32)>>>(Wq, Wk, Wv, Wo);
    split_x_kernel<<<(MROWS * DMODEL / 4) / 256, 256>>>(x);
    gemm_qkv_kernel<<<dim3(DMODEL / 128, MROWS / 128, 3), 256>>>(bq, bk, bv);
    attn_kernel<<<MROWS / 8, 256>>>();
    gemm_out_kernel<<<dim3(DMODEL / 128, MROWS / 128, 1), 256>>>(bo, out);
}

// round 7
// speedup vs baseline: 1.3232x; 1.3232x over previous
#include <cuda_runtime.h>
#include <cuda_bf16.h>
#include <cstdint>

// ---------------------------------------------------------------------------
// Problem constants
// ---------------------------------------------------------------------------
#define BATCH   2
#define SEQ     3072
#define DMODEL  512
#define NHEADS  8
#define DHEAD   64
#define MROWS   (BATCH * SEQ)      // 6144
#define MAXNB   32
#define CAP     256

typedef unsigned long long u64;
typedef unsigned int u32;

// ---------------------------------------------------------------------------
// Scratch (static device memory; no allocations allowed)
// ---------------------------------------------------------------------------
__device__ float g_Q[MROWS * DMODEL];
__device__ float g_K[MROWS * DMODEL];
__device__ float g_V[MROWS * DMODEL];
__device__ int   g_nbr[MROWS * MAXNB];
__device__ int   g_cnt[MROWS];

// bf16 hi/lo splits
__device__ __nv_bfloat16 g_xh[MROWS * DMODEL];
__device__ __nv_bfloat16 g_xl[MROWS * DMODEL];
__device__ __nv_bfloat16 g_ah[MROWS * DMODEL];
__device__ __nv_bfloat16 g_al[MROWS * DMODEL];
// transposed weights [n][k], 4 matrices (q,k,v,o)
__device__ __nv_bfloat16 g_wth[4 * DMODEL * DMODEL];
__device__ __nv_bfloat16 g_wtl[4 * DMODEL * DMODEL];

// ---------------------------------------------------------------------------
// helpers
// ---------------------------------------------------------------------------
__device__ __forceinline__ void split1(float v, __nv_bfloat16& h, __nv_bfloat16& l) {
    h = __float2bfloat16(v);
    l = __float2bfloat16(v - __bfloat162float(h));
}

// ---------------------------------------------------------------------------
// Merged prep kernel: z=0..3 -> transpose+split W_z ; z=4 -> split x.
// grid (16,16,5), block (32,32).
// ---------------------------------------------------------------------------
__global__ void __launch_bounds__(1024)
prep_kernel(const float* __restrict__ x,
            const float* __restrict__ Wq, const float* __restrict__ Wk,
            const float* __restrict__ Wv, const float* __restrict__ Wo)
{
    if (blockIdx.z < 4) {
        __shared__ float t[32][33];
        const float* W = (blockIdx.z == 0) ? Wq : (blockIdx.z == 1) ? Wk
                       : (blockIdx.z == 2) ? Wv : Wo;
        __nv_bfloat16* Th = g_wth + blockIdx.z * DMODEL * DMODEL;
        __nv_bfloat16* Tl = g_wtl + blockIdx.z * DMODEL * DMODEL;

        const int n = blockIdx.x * 32 + threadIdx.x;
        const int k = blockIdx.y * 32 + threadIdx.y;
        t[threadIdx.y][threadIdx.x] = W[k * DMODEL + n];
        __syncthreads();
        const int no = blockIdx.x * 32 + threadIdx.y;
        const int ko = blockIdx.y * 32 + threadIdx.x;
        const float v = t[threadIdx.x][threadIdx.y];
        __nv_bfloat16 h, l; split1(v, h, l);
        Th[no * DMODEL + ko] = h;
        Tl[no * DMODEL + ko] = l;
    } else {
        // split x: 256 blocks * 1024 threads * 3 float4 = 786432 float4
        const int tid = threadIdx.y * 32 + threadIdx.x;
        const int blk = blockIdx.y * 16 + blockIdx.x;
        #pragma unroll
        for (int r = 0; r < 3; ++r) {
            const int i = (blk * 3 + r) * 1024 + tid;   // float4 index
            const float4 v = ((const float4*)x)[i];
            __nv_bfloat16 h0, h1, h2, h3, l0, l1, l2, l3;
            split1(v.x, h0, l0); split1(v.y, h1, l1);
            split1(v.z, h2, l2); split1(v.w, h3, l3);
            __nv_bfloat162* hp = (__nv_bfloat162*)g_xh;
            __nv_bfloat162* lp = (__nv_bfloat162*)g_xl;
            hp[2 * i]     = __nv_bfloat162(h0, h1);
            hp[2 * i + 1] = __nv_bfloat162(h2, h3);
            lp[2 * i]     = __nv_bfloat162(l0, l1);
            lp[2 * i + 1] = __nv_bfloat162(l2, l3);
        }
    }
}

// ---------------------------------------------------------------------------
// Tensor-core GEMM — exact Round-3 body (measured fastest: qkv 109.3us).
// C = A @ Wt^T + bias, 3-term bf16 split (Ah*Bh + Al*Bh + Ah*Bl).
// CTA 128x128, BK=32, 8 warps (4M x 2N), warp tile 32x64, scalar LDS frags.
// ---------------------------------------------------------------------------
#define ASTR 40    // smem row stride in bf16 elems (80B)

__device__ __forceinline__ void mma16816(float* c, const u32* a, u32 b0, u32 b1) {
    asm volatile(
        "mma.sync.aligned.m16n8k16.row.col.f32.bf16.bf16.f32 "
        "{%0,%1,%2,%3}, {%4,%5,%6,%7}, {%8,%9}, {%0,%1,%2,%3};"
        : "+f"(c[0]), "+f"(c[1]), "+f"(c[2]), "+f"(c[3])
        : "r"(a[0]), "r"(a[1]), "r"(a[2]), "r"(a[3]), "r"(b0), "r"(b1));
}

__device__ __forceinline__ void tc_gemm_body(const __nv_bfloat16* __restrict__ Ah,
                                             const __nv_bfloat16* __restrict__ Al,
                                             const __nv_bfloat16* __restrict__ Bh,
                                             const __nv_bfloat16* __restrict__ Bl,
                                             const float* __restrict__ bias,
                                             float* __restrict__ C)
{
    __shared__ __nv_bfloat16 sAh[128 * ASTR];
    __shared__ __nv_bfloat16 sAl[128 * ASTR];
    __shared__ __nv_bfloat16 sBh[128 * ASTR];
    __shared__ __nv_bfloat16 sBl[128 * ASTR];

    const int tid  = threadIdx.x;
    const int w    = tid >> 5;
    const int lane = tid & 31;
    const int g    = lane >> 2;       // 0..7
    const int t2   = (lane & 3) * 2;  // 0,2,4,6
    const int wm   = w & 3;           // M warp (32 rows)
    const int wn   = w >> 2;          // N warp (64 cols)
    const int m0   = blockIdx.y * 128;
    const int n0   = blockIdx.x * 128;

    const int lr  = tid >> 2;
    const int lc  = (tid & 3) * 8;

    float acc[2][8][4];
    #pragma unroll
    for (int i = 0; i < 2; ++i)
        #pragma unroll
        for (int j = 0; j < 8; ++j)
            #pragma unroll
            for (int q = 0; q < 4; ++q) acc[i][j][q] = 0.f;

    for (int kc = 0; kc < DMODEL / 32; ++kc) {
        const size_t eA0 = (size_t)(m0 + lr) * DMODEL + kc * 32 + lc;
        const size_t eA1 = eA0 + (size_t)64 * DMODEL;
        const size_t eB0 = (size_t)(n0 + lr) * DMODEL + kc * 32 + lc;
        const size_t eB1 = eB0 + (size_t)64 * DMODEL;
        const uint4 vah0 = *(const uint4*)(Ah + eA0);
        const uint4 vah1 = *(const uint4*)(Ah + eA1);
        const uint4 val0 = *(const uint4*)(Al + eA0);
        const uint4 val1 = *(const uint4*)(Al + eA1);
        const uint4 vbh0 = *(const uint4*)(Bh + eB0);
        const uint4 vbh1 = *(const uint4*)(Bh + eB1);
        const uint4 vbl0 = *(const uint4*)(Bl + eB0);
        const uint4 vbl1 = *(const uint4*)(Bl + eB1);

        __syncthreads();   // previous tile fully consumed
        *(uint4*)(sAh + lr * ASTR + lc)        = vah0;
        *(uint4*)(sAh + (lr + 64) * ASTR + lc) = vah1;
        *(uint4*)(sAl + lr * ASTR + lc)        = val0;
        *(uint4*)(sAl + (lr + 64) * ASTR + lc) = val1;
        *(uint4*)(sBh + lr * ASTR + lc)        = vbh0;
        *(uint4*)(sBh + (lr + 64) * ASTR + lc) = vbh1;
        *(uint4*)(sBl + lr * ASTR + lc)        = vbl0;
        *(uint4*)(sBl + (lr + 64) * ASTR + lc) = vbl1;
        __syncthreads();

        #pragma unroll
        for (int ks = 0; ks < 32; ks += 16) {
            u32 ah[2][4], al[2][4];
            #pragma unroll
            for (int ma = 0; ma < 2; ++ma) {
                const int row = wm * 32 + ma * 16 + g;
                ah[ma][0] = *(const u32*)(sAh + row * ASTR + ks + t2);
                ah[ma][1] = *(const u32*)(sAh + (row + 8) * ASTR + ks + t2);
                ah[ma][2] = *(const u32*)(sAh + row * ASTR + ks + t2 + 8);
                ah[ma][3] = *(const u32*)(sAh + (row + 8) * ASTR + ks + t2 + 8);
                al[ma][0] = *(const u32*)(sAl + row * ASTR + ks + t2);
                al[ma][1] = *(const u32*)(sAl + (row + 8) * ASTR + ks + t2);
                al[ma][2] = *(const u32*)(sAl + row * ASTR + ks + t2 + 8);
                al[ma][3] = *(const u32*)(sAl + (row + 8) * ASTR + ks + t2 + 8);
            }
            #pragma unroll
            for (int na = 0; na < 8; ++na) {
                const int nrow = wn * 64 + na * 8 + g;
                const u32 bh0 = *(const u32*)(sBh + nrow * ASTR + ks + t2);
                const u32 bh1 = *(const u32*)(sBh + nrow * ASTR + ks + t2 + 8);
                const u32 bl0 = *(const u32*)(sBl + nrow * ASTR + ks + t2);
                const u32 bl1 = *(const u32*)(sBl + nrow * ASTR + ks + t2 + 8);
                #pragma unroll
                for (int ma = 0; ma < 2; ++ma) {
                    mma16816(acc[ma][na], ah[ma], bh0, bh1);
                    mma16816(acc[ma][na], al[ma], bh0, bh1);
                    mma16816(acc[ma][na], ah[ma], bl0, bl1);
                }
            }
        }
    }

    // epilogue
    #pragma unroll
    for (int ma = 0; ma < 2; ++ma) {
        const int row = m0 + wm * 32 + ma * 16 + g;
        #pragma unroll
        for (int na = 0; na < 8; ++na) {
            const int col = n0 + wn * 64 + na * 8 + t2;
            const float b0 = bias[col], b1 = bias[col + 1];
            float2 o0; o0.x = acc[ma][na][0] + b0; o0.y = acc[ma][na][1] + b1;
            float2 o1; o1.x = acc[ma][na][2] + b0; o1.y = acc[ma][na][3] + b1;
            *(float2*)(C + (size_t)row * DMODEL + col) = o0;
            *(float2*)(C + (size_t)(row + 8) * DMODEL + col) = o1;
        }
    }
}

__global__ void __launch_bounds__(256, 2)
gemm_qkv_kernel(const float* __restrict__ bq, const float* __restrict__ bk,
                const float* __restrict__ bv)
{
    const int z = blockIdx.z;
    const __nv_bfloat16* Bh = g_wth + (size_t)z * DMODEL * DMODEL;
    const __nv_bfloat16* Bl = g_wtl + (size_t)z * DMODEL * DMODEL;
    const float* bias = (z == 0) ? bq : (z == 1) ? bk : bv;
    float* C = (z == 0) ? g_Q : (z == 1) ? g_K : g_V;
    tc_gemm_body(g_xh, g_xl, Bh, Bl, bias, C);
}

__global__ void __launch_bounds__(256, 2)
gemm_out_kernel(const float* __restrict__ bo, float* __restrict__ out)
{
    const __nv_bfloat16* Bh = g_wth + (size_t)3 * DMODEL * DMODEL;
    const __nv_bfloat16* Bl = g_wtl + (size_t)3 * DMODEL * DMODEL;
    tc_gemm_body(g_ah, g_al, Bh, Bl, bo, out);
}

// ---------------------------------------------------------------------------
// Top-k neighbor selection (unchanged — known correct)
// ---------------------------------------------------------------------------
__global__ void __launch_bounds__(256)
topk_kernel(const float* __restrict__ positions)
{
    extern __shared__ float fsm[];
    float* px = fsm;
    float* py = fsm + SEQ;
    float* pz = fsm + 2 * SEQ;
    u64*  cand = (u64*)(fsm + 3 * SEQ);

    const int tid  = threadIdx.x;
    const int warp = tid >> 5;
    const int lane = tid & 31;
    const int r0   = blockIdx.x * 8;
    const int b    = r0 / SEQ;
    const int sbase = b * SEQ;

    for (int i = tid; i < SEQ; i += 256) {
        const float* p = positions + (size_t)(sbase + i) * 3;
        px[i] = p[0]; py[i] = p[1]; pz[i] = p[2];
    }
    __syncthreads();

    const int row = r0 + warp;
    const int si  = row - sbase;
    const float qx = px[si], qy = py[si], qz = pz[si];
    u64* mycand = cand + warp * CAP;

    int cnt = 0;
    for (int t = 0; t < SEQ / 32; ++t) {
        const int j = t * 32 + lane;
        const float dx = px[j] - qx, dy = py[j] - qy, dz = pz[j] - qz;
        const float dist = sqrtf(dx * dx + dy * dy + dz * dz);
        const bool in = dist < 0.5f;
        const unsigned msk = __ballot_sync(0xffffffffu, in);
        if (in) {
            const int pos = cnt + __popc(msk & ((1u << lane) - 1u));
            if (pos < CAP)
                mycand[pos] = ((u64)__float_as_uint(dist) << 32) | (unsigned)j;
        }
        cnt += __popc(msk);
    }
    if (cnt > CAP) cnt = CAP;
    __syncwarp();

    if (cnt <= MAXNB) {
        if (lane < cnt)
            g_nbr[row * MAXNB + lane] = sbase + (int)(mycand[lane] & 0xffffffffull);
        if (lane == 0) g_cnt[row] = cnt;
    } else {
        for (int sel = 0; sel < MAXNB; ++sel) {
            u64 best = ~0ull; int bslot = 0;
            for (int s2 = lane; s2 < cnt; s2 += 32) {
                const u64 kk = mycand[s2];
                if (kk < best) { best = kk; bslot = s2; }
            }
            #pragma unroll
            for (int off = 16; off; off >>= 1) {
                const u64 ob = __shfl_xor_sync(0xffffffffu, best, off);
                const int os = __shfl_xor_sync(0xffffffffu, bslot, off);
                if (ob < best) { best = ob; bslot = os; }
            }
            if (lane == 0) {
                g_nbr[row * MAXNB + sel] = sbase + (int)(best & 0xffffffffull);
                mycand[bslot] = ~0ull;
            }
            __syncwarp();
        }
        if (lane == 0) g_cnt[row] = MAXNB;
    }
}

// ---------------------------------------------------------------------------
// Sparse attention — exact R3 structure (measured fastest) + fused hi/lo
// split epilogue. One CTA per query row, warp = head, lane = neighbor for
// QK; AV via shfl broadcast, lane owns 2 output dims.
// ---------------------------------------------------------------------------
__global__ void __launch_bounds__(256)
attn_kernel()
{
    const int row = blockIdx.x;
    __shared__ int   s_nbr[MAXNB];
    __shared__ float s_q[NHEADS][DHEAD];

    const int tid  = threadIdx.x;
    const int h    = tid >> 5;
    const int lane = tid & 31;
    const int m    = g_cnt[row];

    if (tid < MAXNB)
        s_nbr[tid] = (tid < m) ? g_nbr[row * MAXNB + tid] : 0;

    const float2 q2 = *(const float2*)&g_Q[(size_t)row * DMODEL + h * DHEAD + lane * 2];
    ((float2*)s_q[h])[lane] = q2;
    __syncthreads();

    float score = __int_as_float(0xff800000);
    if (lane < m) {
        const float4* kp = (const float4*)&g_K[(size_t)s_nbr[lane] * DMODEL + h * DHEAD];
        const float4* qp = (const float4*)&s_q[h][0];
        float acc = 0.f;
        #pragma unroll
        for (int c = 0; c < DHEAD / 4; ++c) {
            const float4 kv = kp[c];
            const float4 qv = qp[c];
            acc += kv.x * qv.x + kv.y * qv.y + kv.z * qv.z + kv.w * qv.w;
        }
        score = acc * 0.125f;
    }

    float mx = score;
    #pragma unroll
    for (int off = 16; off; off >>= 1)
        mx = fmaxf(mx, __shfl_xor_sync(0xffffffffu, mx, off));
    float p = __expf(score - mx);
    float sm = p;
    #pragma unroll
    for (int off = 16; off; off >>= 1)
        sm += __shfl_xor_sync(0xffffffffu, sm, off);
    const float pn = p / sm;

    float ox = 0.f, oy = 0.f;
    #pragma unroll
    for (int j = 0; j < MAXNB; ++j) {
        const float pj = __shfl_sync(0xffffffffu, pn, j);
        if (j < m) {
            const float2 v2 =
                *(const float2*)&g_V[(size_t)s_nbr[j] * DMODEL + h * DHEAD + lane * 2];
            ox += pj * v2.x;
            oy += pj * v2.y;
        }
    }

    // fused bf16 hi/lo split of attention output (feeds gemm_out directly)
    __nv_bfloat16 h0, l0, h1, l1;
    split1(ox, h0, l0);
    split1(oy, h1, l1);
    const size_t oidx = (size_t)row * DMODEL + h * DHEAD + lane * 2;
    *(__nv_bfloat162*)&g_ah[oidx] = __nv_bfloat162(h0, h1);
    *(__nv_bfloat162*)&g_al[oidx] = __nv_bfloat162(l0, l1);
}

// ---------------------------------------------------------------------------
// Launch — attn is the 4th launch so the fixed-slot ncu capture profiles it.
// ---------------------------------------------------------------------------
extern "C" void kernel_launch(void* const* d_in, const int* in_sizes, int n_in,
                              void* d_out, int out_size)
{
    (void)in_sizes; (void)n_in; (void)out_size;
    const float* x   = (const float*)d_in[0];
    const float* pos = (const float*)d_in[1];
    const float* Wq  = (const float*)d_in[2];
    const float* bq  = (const float*)d_in[3];
    const float* Wk  = (const float*)d_in[4];
    const float* bk  = (const float*)d_in[5];
    const float* Wv  = (const float*)d_in[6];
    const float* bv  = (const float*)d_in[7];
    const float* Wo  = (const float*)d_in[8];
    const float* bo  = (const float*)d_in[9];
    float* out = (float*)d_out;

    const int topk_smem = 3 * SEQ * 4 + 8 * CAP * 8;
    cudaFuncSetAttribute(topk_kernel,
                         cudaFuncAttributeMaxDynamicSharedMemorySize, topk_smem);

    prep_kernel<<<dim3(16, 16, 5), dim3(32, 32)>>>(x, Wq, Wk, Wv, Wo);   // 1
    topk_kernel<<<MROWS / 8, 256, topk_smem>>>(pos);                      // 2
    gemm_qkv_kernel<<<dim3(DMODEL / 128, MROWS / 128, 3), 256>>>(bq, bk, bv); // 3
    attn_kernel<<<MROWS, 256>>>();                                        // 4 <- profiled
    gemm_out_kernel<<<dim3(DMODEL / 128, MROWS / 128, 1), 256>>>(bo, out);    // 5
}

// round 8
// speedup vs baseline: 1.5069x; 1.1389x over previous
#include <cuda_runtime.h>
#include <cuda_bf16.h>
#include <cstdint>

// ---------------------------------------------------------------------------
// Problem constants
// ---------------------------------------------------------------------------
#define BATCH   2
#define SEQ     3072
#define DMODEL  512
#define NHEADS  8
#define DHEAD   64
#define MROWS   (BATCH * SEQ)      // 6144
#define MAXNB   32
#define CAP     256

typedef unsigned long long u64;
typedef unsigned int u32;

// ---------------------------------------------------------------------------
// Scratch (static device memory; no allocations allowed)
// ---------------------------------------------------------------------------
__device__ float g_Q[MROWS * DMODEL];
__device__ float g_K[MROWS * DMODEL];
__device__ float g_V[MROWS * DMODEL];
__device__ int   g_nbr[MROWS * MAXNB];
__device__ int   g_cnt[MROWS];

// bf16 hi/lo splits
__device__ __nv_bfloat16 g_xh[MROWS * DMODEL];
__device__ __nv_bfloat16 g_xl[MROWS * DMODEL];
__device__ __nv_bfloat16 g_ah[MROWS * DMODEL];
__device__ __nv_bfloat16 g_al[MROWS * DMODEL];
// transposed weights [n][k], 4 matrices (q,k,v,o)
__device__ __nv_bfloat16 g_wth[4 * DMODEL * DMODEL];
__device__ __nv_bfloat16 g_wtl[4 * DMODEL * DMODEL];

// ---------------------------------------------------------------------------
// helpers
// ---------------------------------------------------------------------------
__device__ __forceinline__ void split1(float v, __nv_bfloat16& h, __nv_bfloat16& l) {
    h = __float2bfloat16(v);
    l = __float2bfloat16(v - __bfloat162float(h));
}

// ---------------------------------------------------------------------------
// Merged prep kernel: z=0..3 -> transpose+split W_z ; z=4 -> split x.
// ---------------------------------------------------------------------------
__global__ void __launch_bounds__(1024)
prep_kernel(const float* __restrict__ x,
            const float* __restrict__ Wq, const float* __restrict__ Wk,
            const float* __restrict__ Wv, const float* __restrict__ Wo)
{
    if (blockIdx.z < 4) {
        __shared__ float t[32][33];
        const float* W = (blockIdx.z == 0) ? Wq : (blockIdx.z == 1) ? Wk
                       : (blockIdx.z == 2) ? Wv : Wo;
        __nv_bfloat16* Th = g_wth + blockIdx.z * DMODEL * DMODEL;
        __nv_bfloat16* Tl = g_wtl + blockIdx.z * DMODEL * DMODEL;

        const int n = blockIdx.x * 32 + threadIdx.x;
        const int k = blockIdx.y * 32 + threadIdx.y;
        t[threadIdx.y][threadIdx.x] = W[k * DMODEL + n];
        __syncthreads();
        const int no = blockIdx.x * 32 + threadIdx.y;
        const int ko = blockIdx.y * 32 + threadIdx.x;
        const float v = t[threadIdx.x][threadIdx.y];
        __nv_bfloat16 h, l; split1(v, h, l);
        Th[no * DMODEL + ko] = h;
        Tl[no * DMODEL + ko] = l;
    } else {
        const int tid = threadIdx.y * 32 + threadIdx.x;
        const int blk = blockIdx.y * 16 + blockIdx.x;
        #pragma unroll
        for (int r = 0; r < 3; ++r) {
            const int i = (blk * 3 + r) * 1024 + tid;   // float4 index
            const float4 v = ((const float4*)x)[i];
            __nv_bfloat16 h0, h1, h2, h3, l0, l1, l2, l3;
            split1(v.x, h0, l0); split1(v.y, h1, l1);
            split1(v.z, h2, l2); split1(v.w, h3, l3);
            __nv_bfloat162* hp = (__nv_bfloat162*)g_xh;
            __nv_bfloat162* lp = (__nv_bfloat162*)g_xl;
            hp[2 * i]     = __nv_bfloat162(h0, h1);
            hp[2 * i + 1] = __nv_bfloat162(h2, h3);
            lp[2 * i]     = __nv_bfloat162(l0, l1);
            lp[2 * i + 1] = __nv_bfloat162(l2, l3);
        }
    }
}

// ---------------------------------------------------------------------------
// Tensor-core GEMM — exact Round-3 body (measured fastest: qkv 109.3us).
// ---------------------------------------------------------------------------
#define ASTR 40    // smem row stride in bf16 elems (80B)

__device__ __forceinline__ void mma16816(float* c, const u32* a, u32 b0, u32 b1) {
    asm volatile(
        "mma.sync.aligned.m16n8k16.row.col.f32.bf16.bf16.f32 "
        "{%0,%1,%2,%3}, {%4,%5,%6,%7}, {%8,%9}, {%0,%1,%2,%3};"
        : "+f"(c[0]), "+f"(c[1]), "+f"(c[2]), "+f"(c[3])
        : "r"(a[0]), "r"(a[1]), "r"(a[2]), "r"(a[3]), "r"(b0), "r"(b1));
}

__device__ __forceinline__ void tc_gemm_body(const __nv_bfloat16* __restrict__ Ah,
                                             const __nv_bfloat16* __restrict__ Al,
                                             const __nv_bfloat16* __restrict__ Bh,
                                             const __nv_bfloat16* __restrict__ Bl,
                                             const float* __restrict__ bias,
                                             float* __restrict__ C)
{
    __shared__ __nv_bfloat16 sAh[128 * ASTR];
    __shared__ __nv_bfloat16 sAl[128 * ASTR];
    __shared__ __nv_bfloat16 sBh[128 * ASTR];
    __shared__ __nv_bfloat16 sBl[128 * ASTR];

    const int tid  = threadIdx.x;
    const int w    = tid >> 5;
    const int lane = tid & 31;
    const int g    = lane >> 2;       // 0..7
    const int t2   = (lane & 3) * 2;  // 0,2,4,6
    const int wm   = w & 3;           // M warp (32 rows)
    const int wn   = w >> 2;          // N warp (64 cols)
    const int m0   = blockIdx.y * 128;
    const int n0   = blockIdx.x * 128;

    const int lr  = tid >> 2;
    const int lc  = (tid & 3) * 8;

    float acc[2][8][4];
    #pragma unroll
    for (int i = 0; i < 2; ++i)
        #pragma unroll
        for (int j = 0; j < 8; ++j)
            #pragma unroll
            for (int q = 0; q < 4; ++q) acc[i][j][q] = 0.f;

    for (int kc = 0; kc < DMODEL / 32; ++kc) {
        const size_t eA0 = (size_t)(m0 + lr) * DMODEL + kc * 32 + lc;
        const size_t eA1 = eA0 + (size_t)64 * DMODEL;
        const size_t eB0 = (size_t)(n0 + lr) * DMODEL + kc * 32 + lc;
        const size_t eB1 = eB0 + (size_t)64 * DMODEL;
        const uint4 vah0 = *(const uint4*)(Ah + eA0);
        const uint4 vah1 = *(const uint4*)(Ah + eA1);
        const uint4 val0 = *(const uint4*)(Al + eA0);
        const uint4 val1 = *(const uint4*)(Al + eA1);
        const uint4 vbh0 = *(const uint4*)(Bh + eB0);
        const uint4 vbh1 = *(const uint4*)(Bh + eB1);
        const uint4 vbl0 = *(const uint4*)(Bl + eB0);
        const uint4 vbl1 = *(const uint4*)(Bl + eB1);

        __syncthreads();   // previous tile fully consumed
        *(uint4*)(sAh + lr * ASTR + lc)        = vah0;
        *(uint4*)(sAh + (lr + 64) * ASTR + lc) = vah1;
        *(uint4*)(sAl + lr * ASTR + lc)        = val0;
        *(uint4*)(sAl + (lr + 64) * ASTR + lc) = val1;
        *(uint4*)(sBh + lr * ASTR + lc)        = vbh0;
        *(uint4*)(sBh + (lr + 64) * ASTR + lc) = vbh1;
        *(uint4*)(sBl + lr * ASTR + lc)        = vbl0;
        *(uint4*)(sBl + (lr + 64) * ASTR + lc) = vbl1;
        __syncthreads();

        #pragma unroll
        for (int ks = 0; ks < 32; ks += 16) {
            u32 ah[2][4], al[2][4];
            #pragma unroll
            for (int ma = 0; ma < 2; ++ma) {
                const int row = wm * 32 + ma * 16 + g;
                ah[ma][0] = *(const u32*)(sAh + row * ASTR + ks + t2);
                ah[ma][1] = *(const u32*)(sAh + (row + 8) * ASTR + ks + t2);
                ah[ma][2] = *(const u32*)(sAh + row * ASTR + ks + t2 + 8);
                ah[ma][3] = *(const u32*)(sAh + (row + 8) * ASTR + ks + t2 + 8);
                al[ma][0] = *(const u32*)(sAl + row * ASTR + ks + t2);
                al[ma][1] = *(const u32*)(sAl + (row + 8) * ASTR + ks + t2);
                al[ma][2] = *(const u32*)(sAl + row * ASTR + ks + t2 + 8);
                al[ma][3] = *(const u32*)(sAl + (row + 8) * ASTR + ks + t2 + 8);
            }
            #pragma unroll
            for (int na = 0; na < 8; ++na) {
                const int nrow = wn * 64 + na * 8 + g;
                const u32 bh0 = *(const u32*)(sBh + nrow * ASTR + ks + t2);
                const u32 bh1 = *(const u32*)(sBh + nrow * ASTR + ks + t2 + 8);
                const u32 bl0 = *(const u32*)(sBl + nrow * ASTR + ks + t2);
                const u32 bl1 = *(const u32*)(sBl + nrow * ASTR + ks + t2 + 8);
                #pragma unroll
                for (int ma = 0; ma < 2; ++ma) {
                    mma16816(acc[ma][na], ah[ma], bh0, bh1);
                    mma16816(acc[ma][na], al[ma], bh0, bh1);
                    mma16816(acc[ma][na], ah[ma], bl0, bl1);
                }
            }
        }
    }

    #pragma unroll
    for (int ma = 0; ma < 2; ++ma) {
        const int row = m0 + wm * 32 + ma * 16 + g;
        #pragma unroll
        for (int na = 0; na < 8; ++na) {
            const int col = n0 + wn * 64 + na * 8 + t2;
            const float b0 = bias[col], b1 = bias[col + 1];
            float2 o0; o0.x = acc[ma][na][0] + b0; o0.y = acc[ma][na][1] + b1;
            float2 o1; o1.x = acc[ma][na][2] + b0; o1.y = acc[ma][na][3] + b1;
            *(float2*)(C + (size_t)row * DMODEL + col) = o0;
            *(float2*)(C + (size_t)(row + 8) * DMODEL + col) = o1;
        }
    }
}

__global__ void __launch_bounds__(256, 2)
gemm_qkv_kernel(const float* __restrict__ bq, const float* __restrict__ bk,
                const float* __restrict__ bv)
{
    const int z = blockIdx.z;
    const __nv_bfloat16* Bh = g_wth + (size_t)z * DMODEL * DMODEL;
    const __nv_bfloat16* Bl = g_wtl + (size_t)z * DMODEL * DMODEL;
    const float* bias = (z == 0) ? bq : (z == 1) ? bk : bv;
    float* C = (z == 0) ? g_Q : (z == 1) ? g_K : g_V;
    tc_gemm_body(g_xh, g_xl, Bh, Bl, bias, C);
}

__global__ void __launch_bounds__(256, 2)
gemm_out_kernel(const float* __restrict__ bo, float* __restrict__ out)
{
    const __nv_bfloat16* Bh = g_wth + (size_t)3 * DMODEL * DMODEL;
    const __nv_bfloat16* Bl = g_wtl + (size_t)3 * DMODEL * DMODEL;
    tc_gemm_body(g_ah, g_al, Bh, Bl, bo, out);
}

// ---------------------------------------------------------------------------
// Top-k neighbor selection (unchanged — known correct)
// ---------------------------------------------------------------------------
__global__ void __launch_bounds__(256)
topk_kernel(const float* __restrict__ positions)
{
    extern __shared__ float fsm[];
    float* px = fsm;
    float* py = fsm + SEQ;
    float* pz = fsm + 2 * SEQ;
    u64*  cand = (u64*)(fsm + 3 * SEQ);

    const int tid  = threadIdx.x;
    const int warp = tid >> 5;
    const int lane = tid & 31;
    const int r0   = blockIdx.x * 8;
    const int b    = r0 / SEQ;
    const int sbase = b * SEQ;

    for (int i = tid; i < SEQ; i += 256) {
        const float* p = positions + (size_t)(sbase + i) * 3;
        px[i] = p[0]; py[i] = p[1]; pz[i] = p[2];
    }
    __syncthreads();

    const int row = r0 + warp;
    const int si  = row - sbase;
    const float qx = px[si], qy = py[si], qz = pz[si];
    u64* mycand = cand + warp * CAP;

    int cnt = 0;
    for (int t = 0; t < SEQ / 32; ++t) {
        const int j = t * 32 + lane;
        const float dx = px[j] - qx, dy = py[j] - qy, dz = pz[j] - qz;
        const float dist = sqrtf(dx * dx + dy * dy + dz * dz);
        const bool in = dist < 0.5f;
        const unsigned msk = __ballot_sync(0xffffffffu, in);
        if (in) {
            const int pos = cnt + __popc(msk & ((1u << lane) - 1u));
            if (pos < CAP)
                mycand[pos] = ((u64)__float_as_uint(dist) << 32) | (unsigned)j;
        }
        cnt += __popc(msk);
    }
    if (cnt > CAP) cnt = CAP;
    __syncwarp();

    if (cnt <= MAXNB) {
        if (lane < cnt)
            g_nbr[row * MAXNB + lane] = sbase + (int)(mycand[lane] & 0xffffffffull);
        if (lane == 0) g_cnt[row] = cnt;
    } else {
        for (int sel = 0; sel < MAXNB; ++sel) {
            u64 best = ~0ull; int bslot = 0;
            for (int s2 = lane; s2 < cnt; s2 += 32) {
                const u64 kk = mycand[s2];
                if (kk < best) { best = kk; bslot = s2; }
            }
            #pragma unroll
            for (int off = 16; off; off >>= 1) {
                const u64 ob = __shfl_xor_sync(0xffffffffu, best, off);
                const int os = __shfl_xor_sync(0xffffffffu, bslot, off);
                if (ob < best) { best = ob; bslot = os; }
            }
            if (lane == 0) {
                g_nbr[row * MAXNB + sel] = sbase + (int)(best & 0xffffffffull);
                mycand[bslot] = ~0ull;
            }
            __syncwarp();
        }
        if (lane == 0) g_cnt[row] = MAXNB;
    }
}

// ---------------------------------------------------------------------------
// Sparse attention v3 — coalesced score phase:
//   QK  : warp w owns neighbors 4w..4w+3; lane owns one contiguous float4 of
//         the 2KB K row (fully coalesced LDG.128, 4 wavefronts/instr instead
//         of 32; each K row read ONCE per CTA instead of 8x). 16-lane
//         butterfly -> heads (2c, 2c+1) per chunk c, scores to padded smem.
//   soft: warp = head, lane = neighbor, from smem (-inf init) — R3 semantics.
//   AV  : unchanged R3 (shfl pn, lane owns 2 dims, coalesced V float2).
//   epilogue: fused bf16 hi/lo split (unchanged).
// ---------------------------------------------------------------------------
__global__ void __launch_bounds__(256)
attn_kernel()
{
    const int row = blockIdx.x;
    __shared__ float s_q[DMODEL];                 // 2 KB
    __shared__ float s_s[NHEADS][MAXNB + 1];      // padded scores
    __shared__ int   s_nbr[MAXNB];

    const int tid  = threadIdx.x;
    const int w    = tid >> 5;
    const int lane = tid & 31;
    const int m    = g_cnt[row];

    if (tid < MAXNB)
        s_nbr[tid] = (tid < m) ? g_nbr[row * MAXNB + tid] : 0;
    // init scores to -inf (NHEADS*MAXNB == 256 == blockDim)
    s_s[w][lane] = __int_as_float(0xff800000);
    // stage q row coalescedly (2 floats per thread)
    *(float2*)&s_q[2 * tid] = *(const float2*)&g_Q[(size_t)row * DMODEL + 2 * tid];
    __syncthreads();

    // ---- QK: warp w -> neighbors 4w..4w+3, fully coalesced row reads
    #pragma unroll
    for (int jj = 0; jj < 4; ++jj) {
        const int j = w * 4 + jj;
        if (j < m) {
            const float* krow = &g_K[(size_t)s_nbr[j] * DMODEL];
            #pragma unroll
            for (int c = 0; c < 4; ++c) {
                const float4 kv = *(const float4*)(krow + (c * 32 + lane) * 4);
                const float4 qv = *(const float4*)(s_q + (c * 32 + lane) * 4);
                float part = kv.x * qv.x + kv.y * qv.y + kv.z * qv.z + kv.w * qv.w;
                // reduce within each 16-lane half (head 2c for lanes 0-15,
                // head 2c+1 for lanes 16-31)
                #pragma unroll
                for (int off = 8; off; off >>= 1)
                    part += __shfl_xor_sync(0xffffffffu, part, off);
                if ((lane & 15) == 0)
                    s_s[2 * c + (lane >> 4)][j] = part * 0.125f;
            }
        }
    }
    __syncthreads();

    // ---- softmax: warp = head, lane = neighbor (R3 semantics)
    const float score = s_s[w][lane];   // -inf where j >= m
    float mx = score;
    #pragma unroll
    for (int off = 16; off; off >>= 1)
        mx = fmaxf(mx, __shfl_xor_sync(0xffffffffu, mx, off));
    float p = __expf(score - mx);
    float sm = p;
    #pragma unroll
    for (int off = 16; off; off >>= 1)
        sm += __shfl_xor_sync(0xffffffffu, sm, off);
    const float pn = p / sm;

    // ---- AV: lane owns dims (2*lane, 2*lane+1) of head w
    float ox = 0.f, oy = 0.f;
    #pragma unroll
    for (int j = 0; j < MAXNB; ++j) {
        const float pj = __shfl_sync(0xffffffffu, pn, j);
        if (j < m) {
            const float2 v2 =
                *(const float2*)&g_V[(size_t)s_nbr[j] * DMODEL + w * DHEAD + lane * 2];
            ox += pj * v2.x;
            oy += pj * v2.y;
        }
    }

    // fused bf16 hi/lo split of attention output (feeds gemm_out directly)
    __nv_bfloat16 h0, l0, h1, l1;
    split1(ox, h0, l0);
    split1(oy, h1, l1);
    const size_t oidx = (size_t)row * DMODEL + w * DHEAD + lane * 2;
    *(__nv_bfloat162*)&g_ah[oidx] = __nv_bfloat162(h0, h1);
    *(__nv_bfloat162*)&g_al[oidx] = __nv_bfloat162(l0, l1);
}

// ---------------------------------------------------------------------------
// Launch — attn stays the 4th launch (fixed-slot ncu capture profiles it).
// ---------------------------------------------------------------------------
extern "C" void kernel_launch(void* const* d_in, const int* in_sizes, int n_in,
                              void* d_out, int out_size)
{
    (void)in_sizes; (void)n_in; (void)out_size;
    const float* x   = (const float*)d_in[0];
    const float* pos = (const float*)d_in[1];
    const float* Wq  = (const float*)d_in[2];
    const float* bq  = (const float*)d_in[3];
    const float* Wk  = (const float*)d_in[4];
    const float* bk  = (const float*)d_in[5];
    const float* Wv  = (const float*)d_in[6];
    const float* bv  = (const float*)d_in[7];
    const float* Wo  = (const float*)d_in[8];
    const float* bo  = (const float*)d_in[9];
    float* out = (float*)d_out;

    const int topk_smem = 3 * SEQ * 4 + 8 * CAP * 8;
    cudaFuncSetAttribute(topk_kernel,
                         cudaFuncAttributeMaxDynamicSharedMemorySize, topk_smem);

    prep_kernel<<<dim3(16, 16, 5), dim3(32, 32)>>>(x, Wq, Wk, Wv, Wo);        // 1
    topk_kernel<<<MROWS / 8, 256, topk_smem>>>(pos);                          // 2
    gemm_qkv_kernel<<<dim3(DMODEL / 128, MROWS / 128, 3), 256>>>(bq, bk, bv); // 3
    attn_kernel<<<MROWS, 256>>>();                                            // 4 <- profiled
    gemm_out_kernel<<<dim3(DMODEL / 128, MROWS / 128, 1), 256>>>(bo, out);    // 5
}

// round 9
// speedup vs baseline: 1.5599x; 1.0352x over previous
#include <cuda_runtime.h>
#include <cuda_bf16.h>
#include <cstdint>

// ---------------------------------------------------------------------------
// Problem constants
// ---------------------------------------------------------------------------
#define BATCH   2
#define SEQ     3072
#define DMODEL  512
#define NHEADS  8
#define DHEAD   64
#define MROWS   (BATCH * SEQ)      // 6144
#define MAXNB   32
#define CAP     256

typedef unsigned long long u64;
typedef unsigned int u32;

// ---------------------------------------------------------------------------
// Scratch (static device memory; no allocations allowed)
// ---------------------------------------------------------------------------
__device__ float g_Q[MROWS * DMODEL];
__device__ float g_K[MROWS * DMODEL];
__device__ float g_V[MROWS * DMODEL];
__device__ int   g_nbr[MROWS * MAXNB];
__device__ int   g_cnt[MROWS];

// bf16 hi/lo splits
__device__ __nv_bfloat16 g_xh[MROWS * DMODEL];
__device__ __nv_bfloat16 g_xl[MROWS * DMODEL];
__device__ __nv_bfloat16 g_ah[MROWS * DMODEL];
__device__ __nv_bfloat16 g_al[MROWS * DMODEL];
// transposed weights [n][k], 4 matrices (q,k,v,o)
__device__ __nv_bfloat16 g_wth[4 * DMODEL * DMODEL];
__device__ __nv_bfloat16 g_wtl[4 * DMODEL * DMODEL];

// ---------------------------------------------------------------------------
// helpers
// ---------------------------------------------------------------------------
__device__ __forceinline__ void split1(float v, __nv_bfloat16& h, __nv_bfloat16& l) {
    h = __float2bfloat16(v);
    l = __float2bfloat16(v - __bfloat162float(h));
}

__global__ void __launch_bounds__(256)
split_x_kernel(const float* __restrict__ x)
{
    const int i = blockIdx.x * blockDim.x + threadIdx.x;   // float4 index
    const float4 v = ((const float4*)x)[i];
    __nv_bfloat16 h0, h1, h2, h3, l0, l1, l2, l3;
    split1(v.x, h0, l0); split1(v.y, h1, l1);
    split1(v.z, h2, l2); split1(v.w, h3, l3);
    __nv_bfloat162* hp = (__nv_bfloat162*)g_xh;
    __nv_bfloat162* lp = (__nv_bfloat162*)g_xl;
    hp[2 * i]     = __nv_bfloat162(h0, h1);
    hp[2 * i + 1] = __nv_bfloat162(h2, h3);
    lp[2 * i]     = __nv_bfloat162(l0, l1);
    lp[2 * i + 1] = __nv_bfloat162(l2, l3);
}

// W[k][n] -> Wt[n][k] hi/lo, 4 matrices via blockIdx.z
__global__ void __launch_bounds__(1024)
transpose_split_kernel(const float* __restrict__ Wq, const float* __restrict__ Wk,
                       const float* __restrict__ Wv, const float* __restrict__ Wo)
{
    __shared__ float t[32][33];
    const float* W = (blockIdx.z == 0) ? Wq : (blockIdx.z == 1) ? Wk
                   : (blockIdx.z == 2) ? Wv : Wo;
    __nv_bfloat16* Th = g_wth + blockIdx.z * DMODEL * DMODEL;
    __nv_bfloat16* Tl = g_wtl + blockIdx.z * DMODEL * DMODEL;

    const int n = blockIdx.x * 32 + threadIdx.x;
    const int k = blockIdx.y * 32 + threadIdx.y;
    t[threadIdx.y][threadIdx.x] = W[k * DMODEL + n];
    __syncthreads();
    const int no = blockIdx.x * 32 + threadIdx.y;
    const int ko = blockIdx.y * 32 + threadIdx.x;
    const float v = t[threadIdx.x][threadIdx.y];
    __nv_bfloat16 h, l; split1(v, h, l);
    Th[no * DMODEL + ko] = h;
    Tl[no * DMODEL + ko] = l;
}

// ---------------------------------------------------------------------------
// Tensor-core GEMM v2 — warp tile 64x64 to double MMAs per smem byte.
// CTA tile 256x128, BK=32, 8 warps (4M x 2N), 256 threads, 1 CTA/SM.
// Per warp per ks: 64 LDS regs -> 96 MMAs (ratio 1.5 vs 1.0 before).
// Loop order: sync; STS(kc); sync; LDG(kc+1); MMA(kc)  — LDG latency hides
// under the ~1500-cycle MMA phase (single smem buffer, no WAR hazard since
// LDG targets registers).
// ---------------------------------------------------------------------------
#define ASTR 40                     // smem row stride in bf16 elems (80B)
#define BM2  256
#define BN2  128
#define SA_E (BM2 * ASTR)           // 10240 elems per A tile
#define SB_E (BN2 * ASTR)           // 5120 elems per B tile
#define GEMM_SMEM ((2 * SA_E + 2 * SB_E) * 2)   // 61440 bytes

__device__ __forceinline__ void mma16816(float* c, const u32* a, u32 b0, u32 b1) {
    asm volatile(
        "mma.sync.aligned.m16n8k16.row.col.f32.bf16.bf16.f32 "
        "{%0,%1,%2,%3}, {%4,%5,%6,%7}, {%8,%9}, {%0,%1,%2,%3};"
        : "+f"(c[0]), "+f"(c[1]), "+f"(c[2]), "+f"(c[3])
        : "r"(a[0]), "r"(a[1]), "r"(a[2]), "r"(a[3]), "r"(b0), "r"(b1));
}

__device__ __forceinline__ void tc_gemm_body(const __nv_bfloat16* __restrict__ Ah,
                                             const __nv_bfloat16* __restrict__ Al,
                                             const __nv_bfloat16* __restrict__ Bh,
                                             const __nv_bfloat16* __restrict__ Bl,
                                             const float* __restrict__ bias,
                                             float* __restrict__ C)
{
    extern __shared__ __nv_bfloat16 dsm[];
    __nv_bfloat16* sAh = dsm;
    __nv_bfloat16* sAl = dsm + SA_E;
    __nv_bfloat16* sBh = dsm + 2 * SA_E;
    __nv_bfloat16* sBl = dsm + 2 * SA_E + SB_E;

    const int tid  = threadIdx.x;
    const int w    = tid >> 5;
    const int lane = tid & 31;
    const int g    = lane >> 2;       // 0..7
    const int t2   = (lane & 3) * 2;  // 0,2,4,6
    const int wm   = w & 3;           // M warp (64 rows)
    const int wn   = w >> 2;          // N warp (64 cols)
    const int m0   = blockIdx.y * BM2;
    const int n0   = blockIdx.x * BN2;

    // loaders: lr = tid/4 (0..63), lc = (tid%4)*8
    const int lr = tid >> 2;
    const int lc = (tid & 3) * 8;

    float acc[4][8][4];
    #pragma unroll
    for (int i = 0; i < 4; ++i)
        #pragma unroll
        for (int j = 0; j < 8; ++j)
            #pragma unroll
            for (int q = 0; q < 4; ++q) acc[i][j][q] = 0.f;

    uint4 rga[8];   // Ah rows lr+64i (i<4), Al rows lr+64i
    uint4 rgb[4];   // Bh rows lr, lr+64 ; Bl rows lr, lr+64

    const size_t baseA = (size_t)(m0 + lr) * DMODEL + lc;
    const size_t baseB = (size_t)(n0 + lr) * DMODEL + lc;

    // preload kc = 0
    #pragma unroll
    for (int i = 0; i < 4; ++i) {
        rga[i]     = *(const uint4*)(Ah + baseA + (size_t)(64 * i) * DMODEL);
        rga[4 + i] = *(const uint4*)(Al + baseA + (size_t)(64 * i) * DMODEL);
    }
    #pragma unroll
    for (int i = 0; i < 2; ++i) {
        rgb[i]     = *(const uint4*)(Bh + baseB + (size_t)(64 * i) * DMODEL);
        rgb[2 + i] = *(const uint4*)(Bl + baseB + (size_t)(64 * i) * DMODEL);
    }

    for (int kc = 0; kc < DMODEL / 32; ++kc) {
        __syncthreads();   // previous MMA phase done reading smem
        #pragma unroll
        for (int i = 0; i < 4; ++i) {
            *(uint4*)(sAh + (lr + 64 * i) * ASTR + lc) = rga[i];
            *(uint4*)(sAl + (lr + 64 * i) * ASTR + lc) = rga[4 + i];
        }
        #pragma unroll
        for (int i = 0; i < 2; ++i) {
            *(uint4*)(sBh + (lr + 64 * i) * ASTR + lc) = rgb[i];
            *(uint4*)(sBl + (lr + 64 * i) * ASTR + lc) = rgb[2 + i];
        }
        __syncthreads();

        // prefetch next tile into registers (hidden under MMA phase)
        if (kc + 1 < DMODEL / 32) {
            const size_t ko = (size_t)(kc + 1) * 32;
            #pragma unroll
            for (int i = 0; i < 4; ++i) {
                rga[i]     = *(const uint4*)(Ah + baseA + ko + (size_t)(64 * i) * DMODEL);
                rga[4 + i] = *(const uint4*)(Al + baseA + ko + (size_t)(64 * i) * DMODEL);
            }
            #pragma unroll
            for (int i = 0; i < 2; ++i) {
                rgb[i]     = *(const uint4*)(Bh + baseB + ko + (size_t)(64 * i) * DMODEL);
                rgb[2 + i] = *(const uint4*)(Bl + baseB + ko + (size_t)(64 * i) * DMODEL);
            }
        }

        // MMA phase
        #pragma unroll
        for (int ks = 0; ks < 32; ks += 16) {
            u32 ah[4][4], al[4][4];
            #pragma unroll
            for (int ma = 0; ma < 4; ++ma) {
                const int row = wm * 64 + ma * 16 + g;
                ah[ma][0] = *(const u32*)(sAh + row * ASTR + ks + t2);
                ah[ma][1] = *(const u32*)(sAh + (row + 8) * ASTR + ks + t2);
                ah[ma][2] = *(const u32*)(sAh + row * ASTR + ks + t2 + 8);
                ah[ma][3] = *(const u32*)(sAh + (row + 8) * ASTR + ks + t2 + 8);
                al[ma][0] = *(const u32*)(sAl + row * ASTR + ks + t2);
                al[ma][1] = *(const u32*)(sAl + (row + 8) * ASTR + ks + t2);
                al[ma][2] = *(const u32*)(sAl + row * ASTR + ks + t2 + 8);
                al[ma][3] = *(const u32*)(sAl + (row + 8) * ASTR + ks + t2 + 8);
            }
            #pragma unroll
            for (int na = 0; na < 8; ++na) {
                const int nrow = wn * 64 + na * 8 + g;
                const u32 bh0 = *(const u32*)(sBh + nrow * ASTR + ks + t2);
                const u32 bh1 = *(const u32*)(sBh + nrow * ASTR + ks + t2 + 8);
                const u32 bl0 = *(const u32*)(sBl + nrow * ASTR + ks + t2);
                const u32 bl1 = *(const u32*)(sBl + nrow * ASTR + ks + t2 + 8);
                #pragma unroll
                for (int ma = 0; ma < 4; ++ma) {
                    mma16816(acc[ma][na], ah[ma], bh0, bh1);
                    mma16816(acc[ma][na], al[ma], bh0, bh1);
                    mma16816(acc[ma][na], ah[ma], bl0, bl1);
                }
            }
        }
    }

    // epilogue
    #pragma unroll
    for (int ma = 0; ma < 4; ++ma) {
        const int row = m0 + wm * 64 + ma * 16 + g;
        #pragma unroll
        for (int na = 0; na < 8; ++na) {
            const int col = n0 + wn * 64 + na * 8 + t2;
            const float b0 = bias[col], b1 = bias[col + 1];
            float2 o0; o0.x = acc[ma][na][0] + b0; o0.y = acc[ma][na][1] + b1;
            float2 o1; o1.x = acc[ma][na][2] + b0; o1.y = acc[ma][na][3] + b1;
            *(float2*)(C + (size_t)row * DMODEL + col) = o0;
            *(float2*)(C + (size_t)(row + 8) * DMODEL + col) = o1;
        }
    }
}

__global__ void __launch_bounds__(256)
gemm_qkv_kernel(const float* __restrict__ bq, const float* __restrict__ bk,
                const float* __restrict__ bv)
{
    const int z = blockIdx.z;
    const __nv_bfloat16* Bh = g_wth + (size_t)z * DMODEL * DMODEL;
    const __nv_bfloat16* Bl = g_wtl + (size_t)z * DMODEL * DMODEL;
    const float* bias = (z == 0) ? bq : (z == 1) ? bk : bv;
    float* C = (z == 0) ? g_Q : (z == 1) ? g_K : g_V;
    tc_gemm_body(g_xh, g_xl, Bh, Bl, bias, C);
}

__global__ void __launch_bounds__(256)
gemm_out_kernel(const float* __restrict__ bo, float* __restrict__ out)
{
    const __nv_bfloat16* Bh = g_wth + (size_t)3 * DMODEL * DMODEL;
    const __nv_bfloat16* Bl = g_wtl + (size_t)3 * DMODEL * DMODEL;
    tc_gemm_body(g_ah, g_al, Bh, Bl, bo, out);
}

// ---------------------------------------------------------------------------
// Top-k neighbor selection (unchanged — known correct)
// ---------------------------------------------------------------------------
__global__ void __launch_bounds__(256)
topk_kernel(const float* __restrict__ positions)
{
    extern __shared__ float fsm[];
    float* px = fsm;
    float* py = fsm + SEQ;
    float* pz = fsm + 2 * SEQ;
    u64*  cand = (u64*)(fsm + 3 * SEQ);

    const int tid  = threadIdx.x;
    const int warp = tid >> 5;
    const int lane = tid & 31;
    const int r0   = blockIdx.x * 8;
    const int b    = r0 / SEQ;
    const int sbase = b * SEQ;

    for (int i = tid; i < SEQ; i += 256) {
        const float* p = positions + (size_t)(sbase + i) * 3;
        px[i] = p[0]; py[i] = p[1]; pz[i] = p[2];
    }
    __syncthreads();

    const int row = r0 + warp;
    const int si  = row - sbase;
    const float qx = px[si], qy = py[si], qz = pz[si];
    u64* mycand = cand + warp * CAP;

    int cnt = 0;
    for (int t = 0; t < SEQ / 32; ++t) {
        const int j = t * 32 + lane;
        const float dx = px[j] - qx, dy = py[j] - qy, dz = pz[j] - qz;
        const float dist = sqrtf(dx * dx + dy * dy + dz * dz);
        const bool in = dist < 0.5f;
        const unsigned msk = __ballot_sync(0xffffffffu, in);
        if (in) {
            const int pos = cnt + __popc(msk & ((1u << lane) - 1u));
            if (pos < CAP)
                mycand[pos] = ((u64)__float_as_uint(dist) << 32) | (unsigned)j;
        }
        cnt += __popc(msk);
    }
    if (cnt > CAP) cnt = CAP;
    __syncwarp();

    if (cnt <= MAXNB) {
        if (lane < cnt)
            g_nbr[row * MAXNB + lane] = sbase + (int)(mycand[lane] & 0xffffffffull);
        if (lane == 0) g_cnt[row] = cnt;
    } else {
        for (int sel = 0; sel < MAXNB; ++sel) {
            u64 best = ~0ull; int bslot = 0;
            for (int s2 = lane; s2 < cnt; s2 += 32) {
                const u64 kk = mycand[s2];
                if (kk < best) { best = kk; bslot = s2; }
            }
            #pragma unroll
            for (int off = 16; off; off >>= 1) {
                const u64 ob = __shfl_xor_sync(0xffffffffu, best, off);
                const int os = __shfl_xor_sync(0xffffffffu, bslot, off);
                if (ob < best) { best = ob; bslot = os; }
            }
            if (lane == 0) {
                g_nbr[row * MAXNB + sel] = sbase + (int)(best & 0xffffffffull);
                mycand[bslot] = ~0ull;
            }
            __syncwarp();
        }
        if (lane == 0) g_cnt[row] = MAXNB;
    }
}

// ---------------------------------------------------------------------------
// Sparse attention — R8 version (measured 69.2us), unchanged.
// ---------------------------------------------------------------------------
__global__ void __launch_bounds__(256)
attn_kernel()
{
    const int row = blockIdx.x;
    __shared__ float s_q[DMODEL];                 // 2 KB
    __shared__ float s_s[NHEADS][MAXNB + 1];      // padded scores
    __shared__ int   s_nbr[MAXNB];

    const int tid  = threadIdx.x;
    const int w    = tid >> 5;
    const int lane = tid & 31;
    const int m    = g_cnt[row];

    if (tid < MAXNB)
        s_nbr[tid] = (tid < m) ? g_nbr[row * MAXNB + tid] : 0;
    s_s[w][lane] = __int_as_float(0xff800000);
    *(float2*)&s_q[2 * tid] = *(const float2*)&g_Q[(size_t)row * DMODEL + 2 * tid];
    __syncthreads();

    // QK: warp w -> neighbors 4w..4w+3, fully coalesced row reads
    #pragma unroll
    for (int jj = 0; jj < 4; ++jj) {
        const int j = w * 4 + jj;
        if (j < m) {
            const float* krow = &g_K[(size_t)s_nbr[j] * DMODEL];
            #pragma unroll
            for (int c = 0; c < 4; ++c) {
                const float4 kv = *(const float4*)(krow + (c * 32 + lane) * 4);
                const float4 qv = *(const float4*)(s_q + (c * 32 + lane) * 4);
                float part = kv.x * qv.x + kv.y * qv.y + kv.z * qv.z + kv.w * qv.w;
                #pragma unroll
                for (int off = 8; off; off >>= 1)
                    part += __shfl_xor_sync(0xffffffffu, part, off);
                if ((lane & 15) == 0)
                    s_s[2 * c + (lane >> 4)][j] = part * 0.125f;
            }
        }
    }
    __syncthreads();

    // softmax: warp = head, lane = neighbor
    const float score = s_s[w][lane];
    float mx = score;
    #pragma unroll
    for (int off = 16; off; off >>= 1)
        mx = fmaxf(mx, __shfl_xor_sync(0xffffffffu, mx, off));
    float p = __expf(score - mx);
    float sm = p;
    #pragma unroll
    for (int off = 16; off; off >>= 1)
        sm += __shfl_xor_sync(0xffffffffu, sm, off);
    const float pn = p / sm;

    // AV: lane owns dims (2*lane, 2*lane+1) of head w
    float ox = 0.f, oy = 0.f;
    #pragma unroll
    for (int j = 0; j < MAXNB; ++j) {
        const float pj = __shfl_sync(0xffffffffu, pn, j);
        if (j < m) {
            const float2 v2 =
                *(const float2*)&g_V[(size_t)s_nbr[j] * DMODEL + w * DHEAD + lane * 2];
            ox += pj * v2.x;
            oy += pj * v2.y;
        }
    }

    // fused bf16 hi/lo split of attention output (feeds gemm_out directly)
    __nv_bfloat16 h0, l0, h1, l1;
    split1(ox, h0, l0);
    split1(oy, h1, l1);
    const size_t oidx = (size_t)row * DMODEL + w * DHEAD + lane * 2;
    *(__nv_bfloat162*)&g_ah[oidx] = __nv_bfloat162(h0, h1);
    *(__nv_bfloat162*)&g_al[oidx] = __nv_bfloat162(l0, l1);
}

// ---------------------------------------------------------------------------
// Launch — gemm_qkv is the 4th launch (fixed-slot ncu capture profiles it).
// ---------------------------------------------------------------------------
extern "C" void kernel_launch(void* const* d_in, const int* in_sizes, int n_in,
                              void* d_out, int out_size)
{
    (void)in_sizes; (void)n_in; (void)out_size;
    const float* x   = (const float*)d_in[0];
    const float* pos = (const float*)d_in[1];
    const float* Wq  = (const float*)d_in[2];
    const float* bq  = (const float*)d_in[3];
    const float* Wk  = (const float*)d_in[4];
    const float* bk  = (const float*)d_in[5];
    const float* Wv  = (const float*)d_in[6];
    const float* bv  = (const float*)d_in[7];
    const float* Wo  = (const float*)d_in[8];
    const float* bo  = (const float*)d_in[9];
    float* out = (float*)d_out;

    const int topk_smem = 3 * SEQ * 4 + 8 * CAP * 8;
    cudaFuncSetAttribute(topk_kernel,
                         cudaFuncAttributeMaxDynamicSharedMemorySize, topk_smem);
    cudaFuncSetAttribute(gemm_qkv_kernel,
                         cudaFuncAttributeMaxDynamicSharedMemorySize, GEMM_SMEM);
    cudaFuncSetAttribute(gemm_out_kernel,
                         cudaFuncAttributeMaxDynamicSharedMemorySize, GEMM_SMEM);

    transpose_split_kernel<<<dim3(16, 16, 4), dim3(32, 32)>>>(Wq, Wk, Wv, Wo);      // 1
    split_x_kernel<<<(MROWS * DMODEL / 4) / 256, 256>>>(x);                         // 2
    topk_kernel<<<MROWS / 8, 256, topk_smem>>>(pos);                                // 3
    gemm_qkv_kernel<<<dim3(DMODEL / BN2, MROWS / BM2, 3), 256, GEMM_SMEM>>>(bq, bk, bv); // 4 <- profiled
    attn_kernel<<<MROWS, 256>>>();                                                  // 5
    gemm_out_kernel<<<dim3(DMODEL / BN2, MROWS / BM2, 1), 256, GEMM_SMEM>>>(bo, out);    // 6
}